// round 8
// baseline (speedup 1.0000x reference)
#include <cuda_runtime.h>
#include <cuda_bf16.h>
#include <cstdint>

#define HID 128
#define NRAD 6
#define NNODES 100000
#define NNODES_PAD 102400     // multiple of 4096 for the scan
#define E_MAX 2000000
#define LDW 68                // smem leading dim in 32-bit words (136 bf16)

// Static scratch (allocation-free per harness rules)
__device__ float g_node[(size_t)NNODES * HID];
__device__ int   g_count[NNODES_PAD];
__device__ int   g_start[NNODES + 1];
__device__ int   g_cursor[NNODES];
__device__ int   g_list[E_MAX];
__device__ int   g_idx_is64;

// ---------------------------------------------------------------------------
// Detect index dtype (int64 LE with small values has zero odd 32-bit words)
// ---------------------------------------------------------------------------
__global__ void detect_idx_kernel(const int* __restrict__ idx32) {
    if (threadIdx.x == 0 && blockIdx.x == 0) {
        int all_zero = 1;
#pragma unroll
        for (int k = 1; k <= 31; k += 2) all_zero &= (idx32[k] == 0);
        g_idx_is64 = all_zero;
    }
}

__device__ __forceinline__ long long load_node(const void* idx, int e, int is64) {
    return is64 ? __ldg(&((const long long*)idx)[e])
                : (long long)__ldg(&((const int*)idx)[e]);
}

// ---------------------------------------------------------------------------
// Counting-sort pipeline: zero counts -> histogram -> scan -> fill lists
// ---------------------------------------------------------------------------
__global__ void zero_count_kernel() {
    int i = blockIdx.x * blockDim.x + threadIdx.x;
    if (i < NNODES_PAD) g_count[i] = 0;
}

__global__ void hist_kernel(const void* __restrict__ idx, int E) {
    int e = blockIdx.x * blockDim.x + threadIdx.x;
    if (e >= E) return;
    long long n = load_node(idx, e, g_idx_is64);
    if ((unsigned long long)n < (unsigned long long)NNODES)
        atomicAdd(&g_count[(int)n], 1);
}

// Single-CTA exclusive scan, 1024 threads, 4096 elements per chunk.
__global__ void scan_kernel() {
    const int tid  = threadIdx.x;
    const int lane = tid & 31;
    const int warp = tid >> 5;
    __shared__ int s_wsum[32];
    __shared__ int s_carry;
    if (tid == 0) s_carry = 0;
    __syncthreads();

    for (int base = 0; base < NNODES_PAD; base += 4096) {
        int i0 = base + tid * 4;
        int4 c = *reinterpret_cast<const int4*>(&g_count[i0]);
        int s0 = c.x, s1 = s0 + c.y, s2 = s1 + c.z, s3 = s2 + c.w;
        int tsum = s3;

        int incl = tsum;
#pragma unroll
        for (int off = 1; off < 32; off <<= 1) {
            int v = __shfl_up_sync(0xFFFFFFFFu, incl, off);
            if (lane >= off) incl += v;
        }
        if (lane == 31) s_wsum[warp] = incl;
        __syncthreads();
        if (warp == 0) {
            int wi = s_wsum[lane];
#pragma unroll
            for (int off = 1; off < 32; off <<= 1) {
                int t = __shfl_up_sync(0xFFFFFFFFu, wi, off);
                if (lane >= off) wi += t;
            }
            s_wsum[lane] = wi;   // inclusive warp sums
        }
        __syncthreads();
        int warp_excl   = (warp == 0) ? 0 : s_wsum[warp - 1];
        int chunk_total = s_wsum[31];
        int carry       = s_carry;
        int tbase = carry + warp_excl + (incl - tsum);

        int e0 = tbase, e1 = tbase + s0, e2 = tbase + s1, e3 = tbase + s2;
        if (i0 + 0 < NNODES) { g_start[i0 + 0] = e0; g_cursor[i0 + 0] = e0; }
        if (i0 + 1 < NNODES) { g_start[i0 + 1] = e1; g_cursor[i0 + 1] = e1; }
        if (i0 + 2 < NNODES) { g_start[i0 + 2] = e2; g_cursor[i0 + 2] = e2; }
        if (i0 + 3 < NNODES) { g_start[i0 + 3] = e3; g_cursor[i0 + 3] = e3; }
        __syncthreads();
        if (tid == 0) s_carry = carry + chunk_total;
        __syncthreads();
    }
    if (tid == 0) g_start[NNODES] = s_carry;
}

__global__ void fill_kernel(const void* __restrict__ idx, int E) {
    int e = blockIdx.x * blockDim.x + threadIdx.x;
    if (e >= E) return;
    long long n = load_node(idx, e, g_idx_is64);
    if ((unsigned long long)n >= (unsigned long long)NNODES) return;
    int pos = atomicAdd(&g_cursor[(int)n], 1);
    if (pos < E_MAX) g_list[pos] = e;
}

// ---------------------------------------------------------------------------
// Gather: one warp per node (grid-stride). Lane l owns h = 4l..4l+3.
// Gate weights in registers; x rows streamed coalesced; single plain store
// per node -> no atomics anywhere in the heavy path.
// ---------------------------------------------------------------------------
__global__ void gather_kernel(const float* __restrict__ x,
                              const float* __restrict__ rbf,
                              const float* __restrict__ Wrbf) {
    const int lane = threadIdx.x & 31;
    const int gwarp  = (blockIdx.x * blockDim.x + threadIdx.x) >> 5;
    const int nwarps = (gridDim.x * blockDim.x) >> 5;
    const int h0 = lane * 4;

    float w[4][NRAD];
#pragma unroll
    for (int j = 0; j < 4; j++)
#pragma unroll
        for (int r = 0; r < NRAD; r++)
            w[j][r] = __ldg(&Wrbf[(h0 + j) * NRAD + r]);

    for (int n = gwarp; n < NNODES; n += nwarps) {
        const int p0 = __ldg(&g_start[n]);
        const int p1 = __ldg(&g_start[n + 1]);
        float a0 = 0.f, a1 = 0.f, a2 = 0.f, a3 = 0.f;

        for (int p = p0; p < p1; p++) {
            int e = __ldg(&g_list[p]);
            const float2* rb2 = reinterpret_cast<const float2*>(rbf + (size_t)e * NRAD);
            float2 ra  = __ldg(rb2 + 0);
            float2 rbv = __ldg(rb2 + 1);
            float2 rc  = __ldg(rb2 + 2);
            float4 xv = *reinterpret_cast<const float4*>(x + (size_t)e * HID + h0);

            float g0 = w[0][0]*ra.x + w[0][1]*ra.y + w[0][2]*rbv.x + w[0][3]*rbv.y + w[0][4]*rc.x + w[0][5]*rc.y;
            float g1 = w[1][0]*ra.x + w[1][1]*ra.y + w[1][2]*rbv.x + w[1][3]*rbv.y + w[1][4]*rc.x + w[1][5]*rc.y;
            float g2 = w[2][0]*ra.x + w[2][1]*ra.y + w[2][2]*rbv.x + w[2][3]*rbv.y + w[2][4]*rc.x + w[2][5]*rc.y;
            float g3 = w[3][0]*ra.x + w[3][1]*ra.y + w[3][2]*rbv.x + w[3][3]*rbv.y + w[3][4]*rc.x + w[3][5]*rc.y;

            a0 += g0 * xv.x;
            a1 += g1 * xv.y;
            a2 += g2 * xv.z;
            a3 += g3 * xv.w;
        }
        *reinterpret_cast<float4*>(g_node + (size_t)n * HID + h0) =
            make_float4(a0, a1, a2, a3);
    }
}

// ===========================================================================
// Phase 2: fused 4-layer MLP via mma.sync split-bf16 (unchanged from R6 WIN)
// ===========================================================================

__device__ __forceinline__ void split2(float a, float b, uint32_t& hi, uint32_t& lo) {
    __nv_bfloat16 ah = __float2bfloat16(a), bh = __float2bfloat16(b);
    float ar = a - __bfloat162float(ah);
    float br = b - __bfloat162float(bh);
    __nv_bfloat162 h2 = __nv_bfloat162(ah, bh);
    __nv_bfloat162 l2 = __nv_bfloat162(__float2bfloat16(ar), __float2bfloat16(br));
    hi = *reinterpret_cast<uint32_t*>(&h2);
    lo = *reinterpret_cast<uint32_t*>(&l2);
}

__device__ __forceinline__ void mma16816(float* acc, const uint32_t* a,
                                         uint32_t b0, uint32_t b1) {
    asm volatile(
        "mma.sync.aligned.m16n8k16.row.col.f32.bf16.bf16.f32 "
        "{%0,%1,%2,%3}, {%4,%5,%6,%7}, {%8,%9}, {%0,%1,%2,%3};"
        : "+f"(acc[0]), "+f"(acc[1]), "+f"(acc[2]), "+f"(acc[3])
        : "r"(a[0]), "r"(a[1]), "r"(a[2]), "r"(a[3]), "r"(b0), "r"(b1));
}

#define TILE_WORDS (128 * LDW)

__global__ void __launch_bounds__(512) mlp_mma_kernel(
    const float* __restrict__ W1, const float* __restrict__ b1,
    const float* __restrict__ W2, const float* __restrict__ b2,
    const float* __restrict__ W3, const float* __restrict__ b3,
    const float* __restrict__ Wout,
    float* __restrict__ out, int nrows)
{
    extern __shared__ uint32_t sw[];
    uint32_t* s_bhi = sw;
    uint32_t* s_blo = sw + TILE_WORDS;
    uint32_t* s_ahi = sw + 2 * TILE_WORDS;
    uint32_t* s_alo = sw + 3 * TILE_WORDS;

    const int tid  = threadIdx.x;
    const int lane = tid & 31;
    const int wid  = tid >> 5;
    const int qr   = lane >> 2;
    const int qc   = lane & 3;
    const int row0 = blockIdx.x * HID;
    const int rloc = (wid & 7) * 16;
    const int nh   = wid >> 3;
    const int mAl  = rloc + qr;
    const int mBl  = mAl + 8;
    const int mA   = row0 + mAl;
    const int mB   = row0 + mBl;

    for (int q = tid; q < HID * (HID / 2); q += 512) {
        int r  = q >> 6;
        int kp = q & 63;
        float2 v = make_float2(0.f, 0.f);
        if (row0 + r < nrows)
            v = *reinterpret_cast<const float2*>(g_node + (size_t)(row0 + r) * HID + 2 * kp);
        uint32_t hi, lo;
        split2(v.x, v.y, hi, lo);
        s_ahi[r * LDW + kp] = hi;
        s_alo[r * LDW + kp] = lo;
    }

    const float* Ws[4] = {W1, W2, W3, Wout};
    const float* Bs[3] = {b1, b2, b3};

    for (int layer = 0; layer < 4; layer++) {
        const float* W = Ws[layer];
        for (int q = tid; q < HID * (HID / 2); q += 512) {
            int n  = q >> 6;
            int kp = q & 63;
            float2 v = *reinterpret_cast<const float2*>(W + n * HID + 2 * kp);
            uint32_t hi, lo;
            split2(v.x, v.y, hi, lo);
            s_bhi[n * LDW + kp] = hi;
            s_blo[n * LDW + kp] = lo;
        }
        __syncthreads();

        float acc[8][4];
#pragma unroll
        for (int t = 0; t < 8; t++)
#pragma unroll
            for (int j = 0; j < 4; j++) acc[t][j] = 0.f;

#pragma unroll
        for (int s = 0; s < 8; s++) {
            int aw  = mAl * LDW + 8 * s + qc;
            int bwr = mBl * LDW + 8 * s + qc;
            uint32_t ahi[4], alo[4];
            ahi[0] = s_ahi[aw];        alo[0] = s_alo[aw];
            ahi[1] = s_ahi[bwr];       alo[1] = s_alo[bwr];
            ahi[2] = s_ahi[aw + 4];    alo[2] = s_alo[aw + 4];
            ahi[3] = s_ahi[bwr + 4];   alo[3] = s_alo[bwr + 4];

            int w0 = (nh * 64 + qr) * LDW + 8 * s + qc;
            uint32_t bh0 = s_bhi[w0], bh1 = s_bhi[w0 + 4];
            uint32_t bl0 = s_blo[w0], bl1 = s_blo[w0 + 4];

#pragma unroll
            for (int t = 0; t < 8; t++) {
                uint32_t cbh0 = bh0, cbh1 = bh1, cbl0 = bl0, cbl1 = bl1;
                if (t < 7) {
                    int wn = (nh * 64 + (t + 1) * 8 + qr) * LDW + 8 * s + qc;
                    bh0 = s_bhi[wn]; bh1 = s_bhi[wn + 4];
                    bl0 = s_blo[wn]; bl1 = s_blo[wn + 4];
                }
                mma16816(acc[t], ahi, cbh0, cbh1);
                mma16816(acc[t], ahi, cbl0, cbl1);
                mma16816(acc[t], alo, cbh0, cbh1);
            }
        }
        __syncthreads();

        if (layer < 3) {
            const float* bias = Bs[layer];
#pragma unroll
            for (int t = 0; t < 8; t++) {
                int c0 = nh * 64 + 8 * t + 2 * qc;
                float bb0 = __ldg(&bias[c0]);
                float bb1 = __ldg(&bias[c0 + 1]);
                float v0 = acc[t][0] + bb0;
                float v1 = acc[t][1] + bb1;
                float v2 = acc[t][2] + bb0;
                float v3 = acc[t][3] + bb1;
                v0 = v0 / (1.f + __expf(-v0));
                v1 = v1 / (1.f + __expf(-v1));
                v2 = v2 / (1.f + __expf(-v2));
                v3 = v3 / (1.f + __expf(-v3));
                uint32_t hA, lA, hB, lB;
                split2(v0, v1, hA, lA);
                split2(v2, v3, hB, lB);
                int wA = mAl * LDW + nh * 32 + 4 * t + qc;
                int wB = mBl * LDW + nh * 32 + 4 * t + qc;
                s_ahi[wA] = hA;  s_alo[wA] = lA;
                s_ahi[wB] = hB;  s_alo[wB] = lB;
            }
        } else {
#pragma unroll
            for (int t = 0; t < 8; t++) {
                int c0 = nh * 64 + 8 * t + 2 * qc;
                if (mA < nrows)
                    *reinterpret_cast<float2*>(out + (size_t)mA * HID + c0) =
                        make_float2(acc[t][0], acc[t][1]);
                if (mB < nrows)
                    *reinterpret_cast<float2*>(out + (size_t)mB * HID + c0) =
                        make_float2(acc[t][2], acc[t][3]);
            }
        }
    }
}

// ---------------------------------------------------------------------------
// Launch
// ---------------------------------------------------------------------------
extern "C" void kernel_launch(void* const* d_in, const int* in_sizes, int n_in,
                              void* d_out, int out_size) {
    const float* x    = (const float*)d_in[0];
    const float* rbf  = (const float*)d_in[1];
    const void*  idx  = d_in[2];
    const float* Wrbf = (const float*)d_in[3];
    const float* W1   = (const float*)d_in[4];
    const float* b1   = (const float*)d_in[5];
    const float* W2   = (const float*)d_in[6];
    const float* b2   = (const float*)d_in[7];
    const float* W3   = (const float*)d_in[8];
    const float* b3   = (const float*)d_in[9];
    const float* Wout = (const float*)d_in[10];

    const int E     = in_sizes[0] / HID;
    const int nrows = out_size / HID;

    detect_idx_kernel<<<1, 32>>>((const int*)idx);
    zero_count_kernel<<<(NNODES_PAD + 255) / 256, 256>>>();
    hist_kernel<<<(E + 255) / 256, 256>>>(idx, E);
    scan_kernel<<<1, 1024>>>();
    fill_kernel<<<(E + 255) / 256, 256>>>(idx, E);
    gather_kernel<<<1184, 256>>>(x, rbf, Wrbf);

    const int smem = 4 * TILE_WORDS * 4;   // 139264 B
    cudaFuncSetAttribute(mlp_mma_kernel, cudaFuncAttributeMaxDynamicSharedMemorySize, smem);
    mlp_mma_kernel<<<(nrows + HID - 1) / HID, 512, smem>>>(
        W1, b1, W2, b2, W3, b3, Wout, (float*)d_out, nrows);
}

// round 9
// speedup vs baseline: 1.0836x; 1.0836x over previous
#include <cuda_runtime.h>
#include <cuda_bf16.h>
#include <cstdint>

#define HID 128
#define NRAD 6
#define NNODES 100000
#define NNODES_PAD 102400     // 25 chunks of 4096
#define NCHUNK 25
#define E_MAX 2000000
#define LDW 68                // smem leading dim in 32-bit words (136 bf16)

// Static scratch (allocation-free per harness rules)
__device__ float g_node[(size_t)NNODES * HID];
__device__ int   g_count[NNODES_PAD];
__device__ int   g_start[NNODES + 1];
__device__ int   g_cursor[NNODES];
__device__ int   g_list[E_MAX];
__device__ int   g_bsum[NCHUNK];
__device__ int   g_boff[NCHUNK];
__device__ int   g_idx_is64;

// ---------------------------------------------------------------------------
// Detect index dtype (int64 LE with small values has zero odd 32-bit words)
// ---------------------------------------------------------------------------
__global__ void detect_idx_kernel(const int* __restrict__ idx32) {
    if (threadIdx.x == 0 && blockIdx.x == 0) {
        int all_zero = 1;
#pragma unroll
        for (int k = 1; k <= 31; k += 2) all_zero &= (idx32[k] == 0);
        g_idx_is64 = all_zero;
    }
}

__device__ __forceinline__ long long load_node(const void* idx, int e, int is64) {
    return is64 ? __ldg(&((const long long*)idx)[e])
                : (long long)__ldg(&((const int*)idx)[e]);
}

// ---------------------------------------------------------------------------
// Counting-sort pipeline
// ---------------------------------------------------------------------------
__global__ void zero_count_kernel() {
    int i = blockIdx.x * blockDim.x + threadIdx.x;
    if (i < NNODES_PAD) g_count[i] = 0;
}

__global__ void hist_kernel(const void* __restrict__ idx, int E) {
    int e = blockIdx.x * blockDim.x + threadIdx.x;
    if (e >= E) return;
    long long n = load_node(idx, e, g_idx_is64);
    if ((unsigned long long)n < (unsigned long long)NNODES)
        atomicAdd(&g_count[(int)n], 1);
}

// Pass 1: per-chunk (4096 elems) sums. 25 CTAs x 1024 threads.
__global__ void scan_bsum_kernel() {
    const int tid  = threadIdx.x;
    const int lane = tid & 31;
    const int warp = tid >> 5;
    __shared__ int s_w[32];

    int i0 = blockIdx.x * 4096 + tid * 4;
    int4 c = *reinterpret_cast<const int4*>(&g_count[i0]);
    int v = c.x + c.y + c.z + c.w;
#pragma unroll
    for (int off = 16; off > 0; off >>= 1)
        v += __shfl_down_sync(0xFFFFFFFFu, v, off);
    if (lane == 0) s_w[warp] = v;
    __syncthreads();
    if (warp == 0) {
        int t = s_w[lane];
#pragma unroll
        for (int off = 16; off > 0; off >>= 1)
            t += __shfl_down_sync(0xFFFFFFFFu, t, off);
        if (lane == 0) g_bsum[blockIdx.x] = t;
    }
}

// Pass 2: 1 warp scans the 25 chunk sums -> exclusive offsets + grand total.
__global__ void scan_boff_kernel() {
    int lane = threadIdx.x;
    int v = (lane < NCHUNK) ? g_bsum[lane] : 0;
    int incl = v;
#pragma unroll
    for (int off = 1; off < 32; off <<= 1) {
        int t = __shfl_up_sync(0xFFFFFFFFu, incl, off);
        if (lane >= off) incl += t;
    }
    if (lane < NCHUNK) g_boff[lane] = incl - v;
    if (lane == NCHUNK - 1) g_start[NNODES] = incl;
}

// Pass 3: full exclusive scan within each chunk, base = g_boff. 25 CTAs.
__global__ void scan_write_kernel() {
    const int tid  = threadIdx.x;
    const int lane = tid & 31;
    const int warp = tid >> 5;
    __shared__ int s_wsum[32];

    int i0 = blockIdx.x * 4096 + tid * 4;
    int4 c = *reinterpret_cast<const int4*>(&g_count[i0]);
    int s0 = c.x, s1 = s0 + c.y, s2 = s1 + c.z, s3 = s2 + c.w;
    int tsum = s3;

    int incl = tsum;
#pragma unroll
    for (int off = 1; off < 32; off <<= 1) {
        int v = __shfl_up_sync(0xFFFFFFFFu, incl, off);
        if (lane >= off) incl += v;
    }
    if (lane == 31) s_wsum[warp] = incl;
    __syncthreads();
    if (warp == 0) {
        int wi = s_wsum[lane];
#pragma unroll
        for (int off = 1; off < 32; off <<= 1) {
            int t = __shfl_up_sync(0xFFFFFFFFu, wi, off);
            if (lane >= off) wi += t;
        }
        s_wsum[lane] = wi;
    }
    __syncthreads();
    int warp_excl = (warp == 0) ? 0 : s_wsum[warp - 1];
    int tbase = g_boff[blockIdx.x] + warp_excl + (incl - tsum);

    int e0 = tbase, e1 = tbase + s0, e2 = tbase + s1, e3 = tbase + s2;
    if (i0 + 0 < NNODES) { g_start[i0 + 0] = e0; g_cursor[i0 + 0] = e0; }
    if (i0 + 1 < NNODES) { g_start[i0 + 1] = e1; g_cursor[i0 + 1] = e1; }
    if (i0 + 2 < NNODES) { g_start[i0 + 2] = e2; g_cursor[i0 + 2] = e2; }
    if (i0 + 3 < NNODES) { g_start[i0 + 3] = e3; g_cursor[i0 + 3] = e3; }
}

__global__ void fill_kernel(const void* __restrict__ idx, int E) {
    int e = blockIdx.x * blockDim.x + threadIdx.x;
    if (e >= E) return;
    long long n = load_node(idx, e, g_idx_is64);
    if ((unsigned long long)n >= (unsigned long long)NNODES) return;
    int pos = atomicAdd(&g_cursor[(int)n], 1);
    if (pos < E_MAX) g_list[pos] = e;
}

// ---------------------------------------------------------------------------
// Gather: one warp per node (grid-stride), 2-edge unrolled for MLP=2.
// ---------------------------------------------------------------------------
__global__ void gather_kernel(const float* __restrict__ x,
                              const float* __restrict__ rbf,
                              const float* __restrict__ Wrbf) {
    const int lane = threadIdx.x & 31;
    const int gwarp  = (blockIdx.x * blockDim.x + threadIdx.x) >> 5;
    const int nwarps = (gridDim.x * blockDim.x) >> 5;
    const int h0 = lane * 4;

    float w[4][NRAD];
#pragma unroll
    for (int j = 0; j < 4; j++)
#pragma unroll
        for (int r = 0; r < NRAD; r++)
            w[j][r] = __ldg(&Wrbf[(h0 + j) * NRAD + r]);

    for (int n = gwarp; n < NNODES; n += nwarps) {
        const int p0 = __ldg(&g_start[n]);
        const int p1 = __ldg(&g_start[n + 1]);
        float a0 = 0.f, a1 = 0.f, a2 = 0.f, a3 = 0.f;

        int p = p0;
        for (; p + 2 <= p1; p += 2) {
            int e0 = __ldg(&g_list[p]);
            int e1 = __ldg(&g_list[p + 1]);
            const float2* q0 = reinterpret_cast<const float2*>(rbf + (size_t)e0 * NRAD);
            const float2* q1 = reinterpret_cast<const float2*>(rbf + (size_t)e1 * NRAD);
            float2 ra0 = __ldg(q0 + 0), rb0 = __ldg(q0 + 1), rc0 = __ldg(q0 + 2);
            float2 ra1 = __ldg(q1 + 0), rb1 = __ldg(q1 + 1), rc1 = __ldg(q1 + 2);
            float4 xv0 = *reinterpret_cast<const float4*>(x + (size_t)e0 * HID + h0);
            float4 xv1 = *reinterpret_cast<const float4*>(x + (size_t)e1 * HID + h0);

            float g00 = w[0][0]*ra0.x + w[0][1]*ra0.y + w[0][2]*rb0.x + w[0][3]*rb0.y + w[0][4]*rc0.x + w[0][5]*rc0.y;
            float g01 = w[1][0]*ra0.x + w[1][1]*ra0.y + w[1][2]*rb0.x + w[1][3]*rb0.y + w[1][4]*rc0.x + w[1][5]*rc0.y;
            float g02 = w[2][0]*ra0.x + w[2][1]*ra0.y + w[2][2]*rb0.x + w[2][3]*rb0.y + w[2][4]*rc0.x + w[2][5]*rc0.y;
            float g03 = w[3][0]*ra0.x + w[3][1]*ra0.y + w[3][2]*rb0.x + w[3][3]*rb0.y + w[3][4]*rc0.x + w[3][5]*rc0.y;
            a0 += g00 * xv0.x;  a1 += g01 * xv0.y;  a2 += g02 * xv0.z;  a3 += g03 * xv0.w;

            float g10 = w[0][0]*ra1.x + w[0][1]*ra1.y + w[0][2]*rb1.x + w[0][3]*rb1.y + w[0][4]*rc1.x + w[0][5]*rc1.y;
            float g11 = w[1][0]*ra1.x + w[1][1]*ra1.y + w[1][2]*rb1.x + w[1][3]*rb1.y + w[1][4]*rc1.x + w[1][5]*rc1.y;
            float g12 = w[2][0]*ra1.x + w[2][1]*ra1.y + w[2][2]*rb1.x + w[2][3]*rb1.y + w[2][4]*rc1.x + w[2][5]*rc1.y;
            float g13 = w[3][0]*ra1.x + w[3][1]*ra1.y + w[3][2]*rb1.x + w[3][3]*rb1.y + w[3][4]*rc1.x + w[3][5]*rc1.y;
            a0 += g10 * xv1.x;  a1 += g11 * xv1.y;  a2 += g12 * xv1.z;  a3 += g13 * xv1.w;
        }
        if (p < p1) {
            int e = __ldg(&g_list[p]);
            const float2* q = reinterpret_cast<const float2*>(rbf + (size_t)e * NRAD);
            float2 ra = __ldg(q + 0), rb = __ldg(q + 1), rc = __ldg(q + 2);
            float4 xv = *reinterpret_cast<const float4*>(x + (size_t)e * HID + h0);
            float g0 = w[0][0]*ra.x + w[0][1]*ra.y + w[0][2]*rb.x + w[0][3]*rb.y + w[0][4]*rc.x + w[0][5]*rc.y;
            float g1 = w[1][0]*ra.x + w[1][1]*ra.y + w[1][2]*rb.x + w[1][3]*rb.y + w[1][4]*rc.x + w[1][5]*rc.y;
            float g2 = w[2][0]*ra.x + w[2][1]*ra.y + w[2][2]*rb.x + w[2][3]*rb.y + w[2][4]*rc.x + w[2][5]*rc.y;
            float g3 = w[3][0]*ra.x + w[3][1]*ra.y + w[3][2]*rb.x + w[3][3]*rb.y + w[3][4]*rc.x + w[3][5]*rc.y;
            a0 += g0 * xv.x;  a1 += g1 * xv.y;  a2 += g2 * xv.z;  a3 += g3 * xv.w;
        }
        *reinterpret_cast<float4*>(g_node + (size_t)n * HID + h0) =
            make_float4(a0, a1, a2, a3);
    }
}

// ===========================================================================
// Phase 2: fused 4-layer MLP via mma.sync split-bf16 (unchanged — R6 WIN)
// ===========================================================================

__device__ __forceinline__ void split2(float a, float b, uint32_t& hi, uint32_t& lo) {
    __nv_bfloat16 ah = __float2bfloat16(a), bh = __float2bfloat16(b);
    float ar = a - __bfloat162float(ah);
    float br = b - __bfloat162float(bh);
    __nv_bfloat162 h2 = __nv_bfloat162(ah, bh);
    __nv_bfloat162 l2 = __nv_bfloat162(__float2bfloat16(ar), __float2bfloat16(br));
    hi = *reinterpret_cast<uint32_t*>(&h2);
    lo = *reinterpret_cast<uint32_t*>(&l2);
}

__device__ __forceinline__ void mma16816(float* acc, const uint32_t* a,
                                         uint32_t b0, uint32_t b1) {
    asm volatile(
        "mma.sync.aligned.m16n8k16.row.col.f32.bf16.bf16.f32 "
        "{%0,%1,%2,%3}, {%4,%5,%6,%7}, {%8,%9}, {%0,%1,%2,%3};"
        : "+f"(acc[0]), "+f"(acc[1]), "+f"(acc[2]), "+f"(acc[3])
        : "r"(a[0]), "r"(a[1]), "r"(a[2]), "r"(a[3]), "r"(b0), "r"(b1));
}

#define TILE_WORDS (128 * LDW)

__global__ void __launch_bounds__(512) mlp_mma_kernel(
    const float* __restrict__ W1, const float* __restrict__ b1,
    const float* __restrict__ W2, const float* __restrict__ b2,
    const float* __restrict__ W3, const float* __restrict__ b3,
    const float* __restrict__ Wout,
    float* __restrict__ out, int nrows)
{
    extern __shared__ uint32_t sw[];
    uint32_t* s_bhi = sw;
    uint32_t* s_blo = sw + TILE_WORDS;
    uint32_t* s_ahi = sw + 2 * TILE_WORDS;
    uint32_t* s_alo = sw + 3 * TILE_WORDS;

    const int tid  = threadIdx.x;
    const int lane = tid & 31;
    const int wid  = tid >> 5;
    const int qr   = lane >> 2;
    const int qc   = lane & 3;
    const int row0 = blockIdx.x * HID;
    const int rloc = (wid & 7) * 16;
    const int nh   = wid >> 3;
    const int mAl  = rloc + qr;
    const int mBl  = mAl + 8;
    const int mA   = row0 + mAl;
    const int mB   = row0 + mBl;

    for (int q = tid; q < HID * (HID / 2); q += 512) {
        int r  = q >> 6;
        int kp = q & 63;
        float2 v = make_float2(0.f, 0.f);
        if (row0 + r < nrows)
            v = *reinterpret_cast<const float2*>(g_node + (size_t)(row0 + r) * HID + 2 * kp);
        uint32_t hi, lo;
        split2(v.x, v.y, hi, lo);
        s_ahi[r * LDW + kp] = hi;
        s_alo[r * LDW + kp] = lo;
    }

    const float* Ws[4] = {W1, W2, W3, Wout};
    const float* Bs[3] = {b1, b2, b3};

    for (int layer = 0; layer < 4; layer++) {
        const float* W = Ws[layer];
        for (int q = tid; q < HID * (HID / 2); q += 512) {
            int n  = q >> 6;
            int kp = q & 63;
            float2 v = *reinterpret_cast<const float2*>(W + n * HID + 2 * kp);
            uint32_t hi, lo;
            split2(v.x, v.y, hi, lo);
            s_bhi[n * LDW + kp] = hi;
            s_blo[n * LDW + kp] = lo;
        }
        __syncthreads();

        float acc[8][4];
#pragma unroll
        for (int t = 0; t < 8; t++)
#pragma unroll
            for (int j = 0; j < 4; j++) acc[t][j] = 0.f;

#pragma unroll
        for (int s = 0; s < 8; s++) {
            int aw  = mAl * LDW + 8 * s + qc;
            int bwr = mBl * LDW + 8 * s + qc;
            uint32_t ahi[4], alo[4];
            ahi[0] = s_ahi[aw];        alo[0] = s_alo[aw];
            ahi[1] = s_ahi[bwr];       alo[1] = s_alo[bwr];
            ahi[2] = s_ahi[aw + 4];    alo[2] = s_alo[aw + 4];
            ahi[3] = s_ahi[bwr + 4];   alo[3] = s_alo[bwr + 4];

            int w0 = (nh * 64 + qr) * LDW + 8 * s + qc;
            uint32_t bh0 = s_bhi[w0], bh1 = s_bhi[w0 + 4];
            uint32_t bl0 = s_blo[w0], bl1 = s_blo[w0 + 4];

#pragma unroll
            for (int t = 0; t < 8; t++) {
                uint32_t cbh0 = bh0, cbh1 = bh1, cbl0 = bl0, cbl1 = bl1;
                if (t < 7) {
                    int wn = (nh * 64 + (t + 1) * 8 + qr) * LDW + 8 * s + qc;
                    bh0 = s_bhi[wn]; bh1 = s_bhi[wn + 4];
                    bl0 = s_blo[wn]; bl1 = s_blo[wn + 4];
                }
                mma16816(acc[t], ahi, cbh0, cbh1);
                mma16816(acc[t], ahi, cbl0, cbl1);
                mma16816(acc[t], alo, cbh0, cbh1);
            }
        }
        __syncthreads();

        if (layer < 3) {
            const float* bias = Bs[layer];
#pragma unroll
            for (int t = 0; t < 8; t++) {
                int c0 = nh * 64 + 8 * t + 2 * qc;
                float bb0 = __ldg(&bias[c0]);
                float bb1 = __ldg(&bias[c0 + 1]);
                float v0 = acc[t][0] + bb0;
                float v1 = acc[t][1] + bb1;
                float v2 = acc[t][2] + bb0;
                float v3 = acc[t][3] + bb1;
                v0 = v0 / (1.f + __expf(-v0));
                v1 = v1 / (1.f + __expf(-v1));
                v2 = v2 / (1.f + __expf(-v2));
                v3 = v3 / (1.f + __expf(-v3));
                uint32_t hA, lA, hB, lB;
                split2(v0, v1, hA, lA);
                split2(v2, v3, hB, lB);
                int wA = mAl * LDW + nh * 32 + 4 * t + qc;
                int wB = mBl * LDW + nh * 32 + 4 * t + qc;
                s_ahi[wA] = hA;  s_alo[wA] = lA;
                s_ahi[wB] = hB;  s_alo[wB] = lB;
            }
        } else {
#pragma unroll
            for (int t = 0; t < 8; t++) {
                int c0 = nh * 64 + 8 * t + 2 * qc;
                if (mA < nrows)
                    *reinterpret_cast<float2*>(out + (size_t)mA * HID + c0) =
                        make_float2(acc[t][0], acc[t][1]);
                if (mB < nrows)
                    *reinterpret_cast<float2*>(out + (size_t)mB * HID + c0) =
                        make_float2(acc[t][2], acc[t][3]);
            }
        }
    }
}

// ---------------------------------------------------------------------------
// Launch
// ---------------------------------------------------------------------------
extern "C" void kernel_launch(void* const* d_in, const int* in_sizes, int n_in,
                              void* d_out, int out_size) {
    const float* x    = (const float*)d_in[0];
    const float* rbf  = (const float*)d_in[1];
    const void*  idx  = d_in[2];
    const float* Wrbf = (const float*)d_in[3];
    const float* W1   = (const float*)d_in[4];
    const float* b1   = (const float*)d_in[5];
    const float* W2   = (const float*)d_in[6];
    const float* b2   = (const float*)d_in[7];
    const float* W3   = (const float*)d_in[8];
    const float* b3   = (const float*)d_in[9];
    const float* Wout = (const float*)d_in[10];

    const int E     = in_sizes[0] / HID;
    const int nrows = out_size / HID;

    detect_idx_kernel<<<1, 32>>>((const int*)idx);
    zero_count_kernel<<<(NNODES_PAD + 255) / 256, 256>>>();
    hist_kernel<<<(E + 255) / 256, 256>>>(idx, E);
    scan_bsum_kernel<<<NCHUNK, 1024>>>();
    scan_boff_kernel<<<1, 32>>>();
    scan_write_kernel<<<NCHUNK, 1024>>>();
    fill_kernel<<<(E + 255) / 256, 256>>>(idx, E);
    gather_kernel<<<1184, 256>>>(x, rbf, Wrbf);

    const int smem = 4 * TILE_WORDS * 4;   // 139264 B
    cudaFuncSetAttribute(mlp_mma_kernel, cudaFuncAttributeMaxDynamicSharedMemorySize, smem);
    mlp_mma_kernel<<<(nrows + HID - 1) / HID, 512, smem>>>(
        W1, b1, W2, b2, W3, b3, Wout, (float*)d_out, nrows);
}

// round 10
// speedup vs baseline: 1.1836x; 1.0923x over previous
#include <cuda_runtime.h>
#include <cuda_bf16.h>
#include <cstdint>

#define HID 128
#define NRAD 6
#define NNODES 100000
#define NNODES_PAD 102400     // 25 chunks of 4096
#define NCHUNK 25
#define E_MAX 2000000
#define LDW 72                // smem leading dim in 32-bit words (144 bf16)
#define TILE_WORDS (128 * LDW)

// Static scratch (allocation-free per harness rules)
__device__ float    g_node[(size_t)NNODES * HID];
__device__ int      g_count[NNODES_PAD];
__device__ int      g_start[NNODES + 1];
__device__ int      g_cursor[NNODES];
__device__ int      g_list[E_MAX];
__device__ int      g_bsum[NCHUNK];
__device__ int      g_boff[NCHUNK];
__device__ int      g_idx_is64;
__device__ uint32_t g_wsplit[4][2][TILE_WORDS];   // [layer][hi/lo][row*LDW+word]

// permuted k-word position: pairs {w, w+4} become adjacent {2(w&3), 2(w&3)+1}
__device__ __host__ __forceinline__ int permw(int w) {
    return ((w >> 3) << 3) + 2 * (w & 3) + ((w >> 2) & 1);
}

// ---------------------------------------------------------------------------
// Detect index dtype (int64 LE with small values has zero odd 32-bit words)
// ---------------------------------------------------------------------------
__global__ void detect_idx_kernel(const int* __restrict__ idx32) {
    if (threadIdx.x == 0 && blockIdx.x == 0) {
        int all_zero = 1;
#pragma unroll
        for (int k = 1; k <= 31; k += 2) all_zero &= (idx32[k] == 0);
        g_idx_is64 = all_zero;
    }
}

__device__ __forceinline__ long long load_node(const void* idx, int e, int is64) {
    return is64 ? __ldg(&((const long long*)idx)[e])
                : (long long)__ldg(&((const int*)idx)[e]);
}

__device__ __forceinline__ void split2(float a, float b, uint32_t& hi, uint32_t& lo) {
    __nv_bfloat16 ah = __float2bfloat16(a), bh = __float2bfloat16(b);
    float ar = a - __bfloat162float(ah);
    float br = b - __bfloat162float(bh);
    __nv_bfloat162 h2 = __nv_bfloat162(ah, bh);
    __nv_bfloat162 l2 = __nv_bfloat162(__float2bfloat16(ar), __float2bfloat16(br));
    hi = *reinterpret_cast<uint32_t*>(&h2);
    lo = *reinterpret_cast<uint32_t*>(&l2);
}

// ---------------------------------------------------------------------------
// Weight pre-split: fp32 [n][k] -> hi/lo bf16 in final permuted smem layout.
// 4 layers x 128 rows x 72 words (words 64..71 zero pad).
// ---------------------------------------------------------------------------
__global__ void prep_weights_kernel(const float* __restrict__ W1,
                                    const float* __restrict__ W2,
                                    const float* __restrict__ W3,
                                    const float* __restrict__ Wout) {
    int q = blockIdx.x * blockDim.x + threadIdx.x;     // 4*128*72 = 36864
    if (q >= 4 * 128 * LDW) return;
    int l = q / (128 * LDW);
    int rem = q - l * (128 * LDW);
    int n = rem / LDW;
    int w = rem - n * LDW;
    const float* Wl = (l == 0) ? W1 : (l == 1) ? W2 : (l == 2) ? W3 : Wout;
    if (w < 64) {
        float2 v = *reinterpret_cast<const float2*>(Wl + n * HID + 2 * w);
        uint32_t hi, lo;
        split2(v.x, v.y, hi, lo);
        int pw = permw(w);
        g_wsplit[l][0][n * LDW + pw] = hi;
        g_wsplit[l][1][n * LDW + pw] = lo;
    } else {
        g_wsplit[l][0][n * LDW + w] = 0u;
        g_wsplit[l][1][n * LDW + w] = 0u;
    }
}

// ---------------------------------------------------------------------------
// Counting-sort pipeline (unchanged from R9 WIN)
// ---------------------------------------------------------------------------
__global__ void zero_count_kernel() {
    int i = blockIdx.x * blockDim.x + threadIdx.x;
    if (i < NNODES_PAD) g_count[i] = 0;
}

__global__ void hist_kernel(const void* __restrict__ idx, int E) {
    int e = blockIdx.x * blockDim.x + threadIdx.x;
    if (e >= E) return;
    long long n = load_node(idx, e, g_idx_is64);
    if ((unsigned long long)n < (unsigned long long)NNODES)
        atomicAdd(&g_count[(int)n], 1);
}

__global__ void scan_bsum_kernel() {
    const int tid  = threadIdx.x;
    const int lane = tid & 31;
    const int warp = tid >> 5;
    __shared__ int s_w[32];

    int i0 = blockIdx.x * 4096 + tid * 4;
    int4 c = *reinterpret_cast<const int4*>(&g_count[i0]);
    int v = c.x + c.y + c.z + c.w;
#pragma unroll
    for (int off = 16; off > 0; off >>= 1)
        v += __shfl_down_sync(0xFFFFFFFFu, v, off);
    if (lane == 0) s_w[warp] = v;
    __syncthreads();
    if (warp == 0) {
        int t = s_w[lane];
#pragma unroll
        for (int off = 16; off > 0; off >>= 1)
            t += __shfl_down_sync(0xFFFFFFFFu, t, off);
        if (lane == 0) g_bsum[blockIdx.x] = t;
    }
}

__global__ void scan_boff_kernel() {
    int lane = threadIdx.x;
    int v = (lane < NCHUNK) ? g_bsum[lane] : 0;
    int incl = v;
#pragma unroll
    for (int off = 1; off < 32; off <<= 1) {
        int t = __shfl_up_sync(0xFFFFFFFFu, incl, off);
        if (lane >= off) incl += t;
    }
    if (lane < NCHUNK) g_boff[lane] = incl - v;
    if (lane == NCHUNK - 1) g_start[NNODES] = incl;
}

__global__ void scan_write_kernel() {
    const int tid  = threadIdx.x;
    const int lane = tid & 31;
    const int warp = tid >> 5;
    __shared__ int s_wsum[32];

    int i0 = blockIdx.x * 4096 + tid * 4;
    int4 c = *reinterpret_cast<const int4*>(&g_count[i0]);
    int s0 = c.x, s1 = s0 + c.y, s2 = s1 + c.z, s3 = s2 + c.w;
    int tsum = s3;

    int incl = tsum;
#pragma unroll
    for (int off = 1; off < 32; off <<= 1) {
        int v = __shfl_up_sync(0xFFFFFFFFu, incl, off);
        if (lane >= off) incl += v;
    }
    if (lane == 31) s_wsum[warp] = incl;
    __syncthreads();
    if (warp == 0) {
        int wi = s_wsum[lane];
#pragma unroll
        for (int off = 1; off < 32; off <<= 1) {
            int t = __shfl_up_sync(0xFFFFFFFFu, wi, off);
            if (lane >= off) wi += t;
        }
        s_wsum[lane] = wi;
    }
    __syncthreads();
    int warp_excl = (warp == 0) ? 0 : s_wsum[warp - 1];
    int tbase = g_boff[blockIdx.x] + warp_excl + (incl - tsum);

    int e0 = tbase, e1 = tbase + s0, e2 = tbase + s1, e3 = tbase + s2;
    if (i0 + 0 < NNODES) { g_start[i0 + 0] = e0; g_cursor[i0 + 0] = e0; }
    if (i0 + 1 < NNODES) { g_start[i0 + 1] = e1; g_cursor[i0 + 1] = e1; }
    if (i0 + 2 < NNODES) { g_start[i0 + 2] = e2; g_cursor[i0 + 2] = e2; }
    if (i0 + 3 < NNODES) { g_start[i0 + 3] = e3; g_cursor[i0 + 3] = e3; }
}

__global__ void fill_kernel(const void* __restrict__ idx, int E) {
    int e = blockIdx.x * blockDim.x + threadIdx.x;
    if (e >= E) return;
    long long n = load_node(idx, e, g_idx_is64);
    if ((unsigned long long)n >= (unsigned long long)NNODES) return;
    int pos = atomicAdd(&g_cursor[(int)n], 1);
    if (pos < E_MAX) g_list[pos] = e;
}

// ---------------------------------------------------------------------------
// Gather: one warp per node (grid-stride), 2-edge unrolled (unchanged R9)
// ---------------------------------------------------------------------------
__global__ void gather_kernel(const float* __restrict__ x,
                              const float* __restrict__ rbf,
                              const float* __restrict__ Wrbf) {
    const int lane = threadIdx.x & 31;
    const int gwarp  = (blockIdx.x * blockDim.x + threadIdx.x) >> 5;
    const int nwarps = (gridDim.x * blockDim.x) >> 5;
    const int h0 = lane * 4;

    float w[4][NRAD];
#pragma unroll
    for (int j = 0; j < 4; j++)
#pragma unroll
        for (int r = 0; r < NRAD; r++)
            w[j][r] = __ldg(&Wrbf[(h0 + j) * NRAD + r]);

    for (int n = gwarp; n < NNODES; n += nwarps) {
        const int p0 = __ldg(&g_start[n]);
        const int p1 = __ldg(&g_start[n + 1]);
        float a0 = 0.f, a1 = 0.f, a2 = 0.f, a3 = 0.f;

        int p = p0;
        for (; p + 2 <= p1; p += 2) {
            int e0 = __ldg(&g_list[p]);
            int e1 = __ldg(&g_list[p + 1]);
            const float2* q0 = reinterpret_cast<const float2*>(rbf + (size_t)e0 * NRAD);
            const float2* q1 = reinterpret_cast<const float2*>(rbf + (size_t)e1 * NRAD);
            float2 ra0 = __ldg(q0 + 0), rb0 = __ldg(q0 + 1), rc0 = __ldg(q0 + 2);
            float2 ra1 = __ldg(q1 + 0), rb1 = __ldg(q1 + 1), rc1 = __ldg(q1 + 2);
            float4 xv0 = *reinterpret_cast<const float4*>(x + (size_t)e0 * HID + h0);
            float4 xv1 = *reinterpret_cast<const float4*>(x + (size_t)e1 * HID + h0);

            float g00 = w[0][0]*ra0.x + w[0][1]*ra0.y + w[0][2]*rb0.x + w[0][3]*rb0.y + w[0][4]*rc0.x + w[0][5]*rc0.y;
            float g01 = w[1][0]*ra0.x + w[1][1]*ra0.y + w[1][2]*rb0.x + w[1][3]*rb0.y + w[1][4]*rc0.x + w[1][5]*rc0.y;
            float g02 = w[2][0]*ra0.x + w[2][1]*ra0.y + w[2][2]*rb0.x + w[2][3]*rb0.y + w[2][4]*rc0.x + w[2][5]*rc0.y;
            float g03 = w[3][0]*ra0.x + w[3][1]*ra0.y + w[3][2]*rb0.x + w[3][3]*rb0.y + w[3][4]*rc0.x + w[3][5]*rc0.y;
            a0 += g00 * xv0.x;  a1 += g01 * xv0.y;  a2 += g02 * xv0.z;  a3 += g03 * xv0.w;

            float g10 = w[0][0]*ra1.x + w[0][1]*ra1.y + w[0][2]*rb1.x + w[0][3]*rb1.y + w[0][4]*rc1.x + w[0][5]*rc1.y;
            float g11 = w[1][0]*ra1.x + w[1][1]*ra1.y + w[1][2]*rb1.x + w[1][3]*rb1.y + w[1][4]*rc1.x + w[1][5]*rc1.y;
            float g12 = w[2][0]*ra1.x + w[2][1]*ra1.y + w[2][2]*rb1.x + w[2][3]*rb1.y + w[2][4]*rc1.x + w[2][5]*rc1.y;
            float g13 = w[3][0]*ra1.x + w[3][1]*ra1.y + w[3][2]*rb1.x + w[3][3]*rb1.y + w[3][4]*rc1.x + w[3][5]*rc1.y;
            a0 += g10 * xv1.x;  a1 += g11 * xv1.y;  a2 += g12 * xv1.z;  a3 += g13 * xv1.w;
        }
        if (p < p1) {
            int e = __ldg(&g_list[p]);
            const float2* q = reinterpret_cast<const float2*>(rbf + (size_t)e * NRAD);
            float2 ra = __ldg(q + 0), rb = __ldg(q + 1), rc = __ldg(q + 2);
            float4 xv = *reinterpret_cast<const float4*>(x + (size_t)e * HID + h0);
            float g0 = w[0][0]*ra.x + w[0][1]*ra.y + w[0][2]*rb.x + w[0][3]*rb.y + w[0][4]*rc.x + w[0][5]*rc.y;
            float g1 = w[1][0]*ra.x + w[1][1]*ra.y + w[1][2]*rb.x + w[1][3]*rb.y + w[1][4]*rc.x + w[1][5]*rc.y;
            float g2 = w[2][0]*ra.x + w[2][1]*ra.y + w[2][2]*rb.x + w[2][3]*rb.y + w[2][4]*rc.x + w[2][5]*rc.y;
            float g3 = w[3][0]*ra.x + w[3][1]*ra.y + w[3][2]*rb.x + w[3][3]*rb.y + w[3][4]*rc.x + w[3][5]*rc.y;
            a0 += g0 * xv.x;  a1 += g1 * xv.y;  a2 += g2 * xv.z;  a3 += g3 * xv.w;
        }
        *reinterpret_cast<float4*>(g_node + (size_t)n * HID + h0) =
            make_float4(a0, a1, a2, a3);
    }
}

// ===========================================================================
// Phase 2: fused 4-layer MLP, split-bf16 mma.sync, permuted LDS.64 fragments.
// ===========================================================================

__device__ __forceinline__ void mma16816(float* acc,
                                         uint32_t a0, uint32_t a1, uint32_t a2, uint32_t a3,
                                         uint32_t b0, uint32_t b1) {
    asm volatile(
        "mma.sync.aligned.m16n8k16.row.col.f32.bf16.bf16.f32 "
        "{%0,%1,%2,%3}, {%4,%5,%6,%7}, {%8,%9}, {%0,%1,%2,%3};"
        : "+f"(acc[0]), "+f"(acc[1]), "+f"(acc[2]), "+f"(acc[3])
        : "r"(a0), "r"(a1), "r"(a2), "r"(a3), "r"(b0), "r"(b1));
}

__global__ void __launch_bounds__(512) mlp_mma_kernel(
    const float* __restrict__ b1, const float* __restrict__ b2,
    const float* __restrict__ b3,
    float* __restrict__ out, int nrows)
{
    extern __shared__ __align__(16) uint32_t sw[];
    uint32_t* s_bhi = sw;                      // weights hi (then lo contiguous)
    uint32_t* s_blo = sw + TILE_WORDS;
    uint32_t* s_ahi = sw + 2 * TILE_WORDS;
    uint32_t* s_alo = sw + 3 * TILE_WORDS;

    const int tid  = threadIdx.x;
    const int lane = tid & 31;
    const int wid  = tid >> 5;
    const int qr   = lane >> 2;
    const int qc   = lane & 3;
    const int row0 = blockIdx.x * HID;
    const int rloc = (wid & 7) * 16;
    const int nh   = wid >> 3;
    const int mAl  = rloc + qr;
    const int mBl  = mAl + 8;
    const int mA   = row0 + mAl;
    const int mB   = row0 + mBl;

    // ---- Stage layer-0 activations: g_node fp32 -> hi/lo bf16 (permuted) ----
    for (int q = tid; q < HID * 64; q += 512) {
        int r = q >> 6;
        int w = q & 63;
        float2 v = make_float2(0.f, 0.f);
        if (row0 + r < nrows)
            v = *reinterpret_cast<const float2*>(g_node + (size_t)(row0 + r) * HID + 2 * w);
        uint32_t hi, lo;
        split2(v.x, v.y, hi, lo);
        int pw = permw(w);
        s_ahi[r * LDW + pw] = hi;
        s_alo[r * LDW + pw] = lo;
    }

    const float* Bs[3] = {b1, b2, b3};

    for (int layer = 0; layer < 4; layer++) {
        // ---- Stage weights: straight uint4 copy (hi+lo contiguous) ----
        {
            const uint4* src = reinterpret_cast<const uint4*>(&g_wsplit[layer][0][0]);
            uint4* dst = reinterpret_cast<uint4*>(s_bhi);
            for (int q = tid; q < 2 * TILE_WORDS / 4; q += 512)
                dst[q] = src[q];
        }
        __syncthreads();

        float acc[8][4];
#pragma unroll
        for (int t = 0; t < 8; t++)
#pragma unroll
            for (int j = 0; j < 4; j++) acc[t][j] = 0.f;

#pragma unroll
        for (int s = 0; s < 8; s++) {
            int aoff = 8 * s + 2 * qc;
            uint2 aH0 = *reinterpret_cast<const uint2*>(&s_ahi[mAl * LDW + aoff]);
            uint2 aH1 = *reinterpret_cast<const uint2*>(&s_ahi[mBl * LDW + aoff]);
            uint2 aL0 = *reinterpret_cast<const uint2*>(&s_alo[mAl * LDW + aoff]);
            uint2 aL1 = *reinterpret_cast<const uint2*>(&s_alo[mBl * LDW + aoff]);

            int bbase = (nh * 64 + qr) * LDW + aoff;
            uint2 bH = *reinterpret_cast<const uint2*>(&s_bhi[bbase]);
            uint2 bL = *reinterpret_cast<const uint2*>(&s_blo[bbase]);

#pragma unroll
            for (int t = 0; t < 8; t++) {
                uint2 cbH = bH, cbL = bL;
                if (t < 7) {
                    int bn = bbase + (t + 1) * 8 * LDW;
                    bH = *reinterpret_cast<const uint2*>(&s_bhi[bn]);
                    bL = *reinterpret_cast<const uint2*>(&s_blo[bn]);
                }
                mma16816(acc[t], aH0.x, aH1.x, aH0.y, aH1.y, cbH.x, cbH.y);
                mma16816(acc[t], aH0.x, aH1.x, aH0.y, aH1.y, cbL.x, cbL.y);
                mma16816(acc[t], aL0.x, aL1.x, aL0.y, aL1.y, cbH.x, cbH.y);
            }
        }
        __syncthreads();

        if (layer < 3) {
            const float* bias = Bs[layer];
#pragma unroll
            for (int t = 0; t < 8; t++) {
                int c0 = nh * 64 + 8 * t + 2 * qc;
                float bb0 = __ldg(&bias[c0]);
                float bb1 = __ldg(&bias[c0 + 1]);
                float v0 = acc[t][0] + bb0;
                float v1 = acc[t][1] + bb1;
                float v2 = acc[t][2] + bb0;
                float v3 = acc[t][3] + bb1;
                v0 = v0 / (1.f + __expf(-v0));
                v1 = v1 / (1.f + __expf(-v1));
                v2 = v2 / (1.f + __expf(-v2));
                v3 = v3 / (1.f + __expf(-v3));
                uint32_t hA, lA, hB, lB;
                split2(v0, v1, hA, lA);
                split2(v2, v3, hB, lB);
                int w = nh * 32 + 4 * t + qc;     // k-word index of this pair
                int pw = permw(w);
                s_ahi[mAl * LDW + pw] = hA;  s_alo[mAl * LDW + pw] = lA;
                s_ahi[mBl * LDW + pw] = hB;  s_alo[mBl * LDW + pw] = lB;
            }
        } else {
#pragma unroll
            for (int t = 0; t < 8; t++) {
                int c0 = nh * 64 + 8 * t + 2 * qc;
                if (mA < nrows)
                    *reinterpret_cast<float2*>(out + (size_t)mA * HID + c0) =
                        make_float2(acc[t][0], acc[t][1]);
                if (mB < nrows)
                    *reinterpret_cast<float2*>(out + (size_t)mB * HID + c0) =
                        make_float2(acc[t][2], acc[t][3]);
            }
        }
    }
}

// ---------------------------------------------------------------------------
// Launch
// ---------------------------------------------------------------------------
extern "C" void kernel_launch(void* const* d_in, const int* in_sizes, int n_in,
                              void* d_out, int out_size) {
    const float* x    = (const float*)d_in[0];
    const float* rbf  = (const float*)d_in[1];
    const void*  idx  = d_in[2];
    const float* Wrbf = (const float*)d_in[3];
    const float* W1   = (const float*)d_in[4];
    const float* b1   = (const float*)d_in[5];
    const float* W2   = (const float*)d_in[6];
    const float* b2   = (const float*)d_in[7];
    const float* W3   = (const float*)d_in[8];
    const float* b3   = (const float*)d_in[9];
    const float* Wout = (const float*)d_in[10];

    const int E     = in_sizes[0] / HID;
    const int nrows = out_size / HID;

    detect_idx_kernel<<<1, 32>>>((const int*)idx);
    prep_weights_kernel<<<(4 * 128 * LDW + 255) / 256, 256>>>(W1, W2, W3, Wout);
    zero_count_kernel<<<(NNODES_PAD + 255) / 256, 256>>>();
    hist_kernel<<<(E + 255) / 256, 256>>>(idx, E);
    scan_bsum_kernel<<<NCHUNK, 1024>>>();
    scan_boff_kernel<<<1, 32>>>();
    scan_write_kernel<<<NCHUNK, 1024>>>();
    fill_kernel<<<(E + 255) / 256, 256>>>(idx, E);
    gather_kernel<<<1184, 256>>>(x, rbf, Wrbf);

    const int smem = 4 * TILE_WORDS * 4;   // 147456 B
    cudaFuncSetAttribute(mlp_mma_kernel, cudaFuncAttributeMaxDynamicSharedMemorySize, smem);
    mlp_mma_kernel<<<(nrows + HID - 1) / HID, 512, smem>>>(
        b1, b2, b3, (float*)d_out, nrows);
}